// round 3
// baseline (speedup 1.0000x reference)
#include <cuda_runtime.h>
#include <math.h>
#include <stdint.h>

#define TOKENS     8192
#define MODEL_DIM  4096
#define PROMPT_DIM 64
#define KTOT       (MODEL_DIM + PROMPT_DIM)   // 4160
#define NE         8
#define TPW        8                           // tokens per warp
#define WARPS      8
#define THREADS    256
#define TPB        (TPW * WARPS)               // 64 tokens per CTA
#define WSTRIDE    4164                        // 4160 + 4 pad (word mult of 4 -> 16B aligned rows)
#define W_WORDS    (NE * WSTRIDE)              // 33312 words = 133,248 B
#define CHUNK      128                         // floats per K-chunk (512 B per token)
#define NCHUNK     (MODEL_DIM / CHUNK)         // 32
#define STAGE_WORDS (TPB * CHUNK)              // 8192 words = 32 KB per stage
#define SMEM_BYTES ((W_WORDS + 2 * STAGE_WORDS) * 4)   // 198,784 B

// ---- cp.async helpers ----
__device__ __forceinline__ void cp16(uint32_t smem_addr, const void* gptr) {
    asm volatile("cp.async.cg.shared.global [%0], [%1], 16;\n"
                 :: "r"(smem_addr), "l"(gptr) : "memory");
}
__device__ __forceinline__ void cp_commit() {
    asm volatile("cp.async.commit_group;\n" ::: "memory");
}
template <int N>
__device__ __forceinline__ void cp_wait() {
    asm volatile("cp.async.wait_group %0;\n" :: "n"(N) : "memory");
}
// packed fp32x2 FMA: d = a*b + d (element-wise on the two packed floats)
__device__ __forceinline__ void ffma2(unsigned long long& d,
                                      unsigned long long a,
                                      unsigned long long b) {
    asm("fma.rn.f32x2 %0, %1, %2, %0;" : "+l"(d) : "l"(a), "l"(b));
}
__device__ __forceinline__ float pk_lo(unsigned long long v) {
    return __uint_as_float((unsigned)(v & 0xffffffffull));
}
__device__ __forceinline__ float pk_hi(unsigned long long v) {
    return __uint_as_float((unsigned)(v >> 32));
}

__global__ __launch_bounds__(THREADS, 1)
void topkgate_kernel(const float* __restrict__ x,
                     const float* __restrict__ prompt,
                     const float* __restrict__ W,
                     const float* __restrict__ b,
                     float* __restrict__ out)
{
    extern __shared__ float smem[];
    float* ws = smem;                 // ws[e * WSTRIDE + d] = W[d][e]
    float* xs = smem + W_WORDS;       // two 32 KB x stages

    const int tid = threadIdx.x;

    // ---- Stage W transposed into SMEM (coalesced LDG; conflict-free STS) ----
    for (int i = tid; i < KTOT * NE; i += THREADS) {
        int d = i >> 3;
        int e = i & 7;
        ws[e * WSTRIDE + d] = W[i];
    }
    __syncthreads();

    const int w     = tid >> 5;
    const int lane  = tid & 31;
    const int tbase = blockIdx.x * TPB + w * TPW;   // grid covers TOKENS exactly

    // ---- Staging assignment: 4 lanes per token, 8 x 16B per lane per chunk ----
    const int stok = lane >> 2;                  // this lane stages token stok
    const int soff = (lane & 3) * 16;            // byte offset within 64B group
    const char* gsrc = (const char*)(x + (size_t)(tbase + stok) * MODEL_DIM) + soff;
    const uint32_t sbase =
        (uint32_t)__cvta_generic_to_shared(xs + w * TPW * CHUNK + stok * CHUNK) + soff;

    unsigned long long acc[TPW][NE];             // packed (even,odd)-dim partial sums
#pragma unroll
    for (int m = 0; m < TPW; m++)
#pragma unroll
        for (int e = 0; e < NE; e++) acc[m][e] = 0ull;

    // ---- Prologue: stage chunk 0 into buffer 0 ----
#pragma unroll
    for (int j = 0; j < 8; j++)
        cp16(sbase + j * 64, gsrc + j * 64);
    cp_commit();

    // ---- Mainloop: warp-private double-buffered pipeline ----
    for (int it = 0; it < NCHUNK; ++it) {
        const int s = it & 1;
        __syncwarp();   // all lanes done reading buffer s^1 before overwriting it

        if (it + 1 < NCHUNK) {
            const char* g = gsrc + (size_t)(it + 1) * 512;
            const uint32_t d0 = sbase + (s ^ 1) * (STAGE_WORDS * 4);
#pragma unroll
            for (int j = 0; j < 8; j++)
                cp16(d0 + j * 64, g + j * 64);
            cp_commit();
            cp_wait<1>();    // chunk it ready (chunk it+1 may still be in flight)
        } else {
            cp_wait<0>();
        }
        __syncwarp();   // make all lanes' cp.async data visible warp-wide

        const float* xw = xs + s * STAGE_WORDS + w * TPW * CHUNK;
        const int wsoff = it * CHUNK + 4 * lane;

        ulonglong2 wv[NE];
#pragma unroll
        for (int e = 0; e < NE; e++)
            wv[e] = *(const ulonglong2*)&ws[e * WSTRIDE + wsoff];

#pragma unroll
        for (int m = 0; m < TPW; m++) {
            const ulonglong2 xv = *(const ulonglong2*)&xw[m * CHUNK + 4 * lane];
#pragma unroll
            for (int e = 0; e < NE; e++) {
                ffma2(acc[m][e], xv.x, wv[e].x);
                ffma2(acc[m][e], xv.y, wv[e].y);
            }
        }
    }

    // ---- Collapse packed pairs to scalar accumulators ----
    float accf[TPW][NE];
#pragma unroll
    for (int m = 0; m < TPW; m++)
#pragma unroll
        for (int e = 0; e < NE; e++)
            accf[m][e] = pk_lo(acc[m][e]) + pk_hi(acc[m][e]);

    // ---- Prompt tail: 64 dims, lanes 0..15 take 4 dims each ----
    if (lane < 16) {
        const int po = 4 * lane;
        float4 wp[NE];
#pragma unroll
        for (int e = 0; e < NE; e++)
            wp[e] = *(const float4*)&ws[e * WSTRIDE + MODEL_DIM + po];
#pragma unroll
        for (int m = 0; m < TPW; m++) {
            const float4 pv = *(const float4*)(prompt + (size_t)(tbase + m) * PROMPT_DIM + po);
#pragma unroll
            for (int e = 0; e < NE; e++) {
                accf[m][e] += pv.x * wp[e].x;
                accf[m][e] += pv.y * wp[e].y;
                accf[m][e] += pv.z * wp[e].z;
                accf[m][e] += pv.w * wp[e].w;
            }
        }
    }

    // ---- Warp butterfly reduction over lanes ----
#pragma unroll
    for (int off = 16; off > 0; off >>= 1) {
#pragma unroll
        for (int m = 0; m < TPW; m++)
#pragma unroll
            for (int e = 0; e < NE; e++)
                accf[m][e] += __shfl_xor_sync(0xffffffffu, accf[m][e], off);
    }

    // ---- Epilogue: lane m handles token (tbase + m) ----
    if (lane < TPW) {
        const int t = tbase + lane;

        float lg[NE];
#pragma unroll
        for (int m = 0; m < TPW; m++) {
            if (lane == m) {
#pragma unroll
                for (int e = 0; e < NE; e++) lg[e] = accf[m][e];
            }
        }
#pragma unroll
        for (int e = 0; e < NE; e++) lg[e] += b[e];

        // Top-2 with first-index tie-break (matches jax.lax.top_k)
        int i0 = 0; float m0 = lg[0];
#pragma unroll
        for (int e = 1; e < NE; e++)
            if (lg[e] > m0) { m0 = lg[e]; i0 = e; }
        int i1 = -1; float m1 = -INFINITY;
#pragma unroll
        for (int e = 0; e < NE; e++)
            if (e != i0 && lg[e] > m1) { m1 = lg[e]; i1 = e; }

        // Softmax over 8 (max-subtracted), gather top-2, renormalize with EPS clamp
        float s = 0.0f;
#pragma unroll
        for (int e = 0; e < NE; e++) s += __expf(lg[e] - m0);
        const float g0 = 1.0f / s;
        const float g1 = __expf(m1 - m0) / s;
        const float denom = fmaxf(g0 + g1, 1.1920929e-07f);
        const float r0 = g0 / denom;
        const float r1 = g1 / denom;

        // masks: [T, 2, 8] at offset 0
        float* mrow = out + (size_t)t * 16;
        const float4 z = make_float4(0.f, 0.f, 0.f, 0.f);
        *(float4*)(mrow + 0)  = z;
        *(float4*)(mrow + 4)  = z;
        *(float4*)(mrow + 8)  = z;
        *(float4*)(mrow + 12) = z;
        mrow[i0]     = 1.0f;
        mrow[8 + i1] = 1.0f;

        // gates_s: [T, 2] at offset T*16
        float* grow = out + (size_t)TOKENS * 16 + (size_t)t * 2;
        grow[0] = r0;
        grow[1] = r1;
    }
}

extern "C" void kernel_launch(void* const* d_in, const int* in_sizes, int n_in,
                              void* d_out, int out_size)
{
    const float* x      = (const float*)d_in[0];
    const float* prompt = (const float*)d_in[1];
    const float* W      = (const float*)d_in[2];
    const float* b      = (const float*)d_in[3];
    float* out          = (float*)d_out;

    cudaFuncSetAttribute(topkgate_kernel,
                         cudaFuncAttributeMaxDynamicSharedMemorySize, SMEM_BYTES);

    dim3 grid(TOKENS / TPB);   // 128 blocks, one wave
    topkgate_kernel<<<grid, THREADS, SMEM_BYTES>>>(x, prompt, W, b, out);
}

// round 4
// speedup vs baseline: 1.4275x; 1.4275x over previous
#include <cuda_runtime.h>
#include <math.h>

#define TOKENS     8192
#define MODEL_DIM  4096
#define PROMPT_DIM 64
#define KTOT       (MODEL_DIM + PROMPT_DIM)   // 4160
#define NE         8
#define TPW        4                          // tokens per warp
#define WARPS      16
#define TPB        (TPW * WARPS)              // 64 tokens per block
#define THREADS    512
#define WSTRIDE    4162                       // 4160 + 2 pad (8B-aligned rows, conflict-free)
#define SMEM_BYTES (NE * WSTRIDE * 4)         // 133,184 B
#define CHUNK      64                         // floats per K-chunk (float2 per lane)
#define NIT        (MODEL_DIM / CHUNK)        // 64
#define RING       4                          // prefetch distance 3

__global__ __launch_bounds__(THREADS, 1)
void topkgate_kernel(const float* __restrict__ x,
                     const float* __restrict__ prompt,
                     const float* __restrict__ W,
                     const float* __restrict__ b,
                     float* __restrict__ out)
{
    extern __shared__ float ws[];   // ws[e * WSTRIDE + d] = W[d][e]

    const int tid = threadIdx.x;

    // ---- Stage W transposed into SMEM (coalesced LDG; conflict-free STS) ----
    for (int i = tid; i < KTOT * NE; i += THREADS) {
        int d = i >> 3;
        int e = i & 7;
        ws[e * WSTRIDE + d] = W[i];
    }
    __syncthreads();

    const int w     = tid >> 5;
    const int lane  = tid & 31;
    const int tbase = blockIdx.x * TPB + w * TPW;   // grid covers TOKENS exactly

    const float* xr[TPW];
#pragma unroll
    for (int m = 0; m < TPW; m++)
        xr[m] = x + (size_t)(tbase + m) * MODEL_DIM + 2 * lane;

    float acc[TPW][NE];
#pragma unroll
    for (int m = 0; m < TPW; m++)
#pragma unroll
        for (int e = 0; e < NE; e++) acc[m][e] = 0.0f;

    // ---- 4-deep register ring, prefetch distance 3 ----
    float2 buf[RING][TPW];
#pragma unroll
    for (int p = 0; p < RING - 1; p++)
#pragma unroll
        for (int m = 0; m < TPW; m++)
            buf[p][m] = __ldcs((const float2*)(xr[m] + p * CHUNK));

    for (int it = 0; it < NIT; it += RING) {
#pragma unroll
        for (int u = 0; u < RING; u++) {
            const int j = it + u;

            // Prefetch chunk j+3 into ring slot (u+3)&3
            if (j + (RING - 1) < NIT) {
#pragma unroll
                for (int m = 0; m < TPW; m++)
                    buf[(u + RING - 1) & (RING - 1)][m] =
                        __ldcs((const float2*)(xr[m] + (j + RING - 1) * CHUNK));
            }

            // W slice for chunk j: float2 per expert, conflict-free LDS.64
            const int wsoff = j * CHUNK + 2 * lane;
            float2 wv[NE];
#pragma unroll
            for (int e = 0; e < NE; e++)
                wv[e] = *(const float2*)&ws[e * WSTRIDE + wsoff];

#pragma unroll
            for (int m = 0; m < TPW; m++) {
                const float2 xv = buf[u][m];
#pragma unroll
                for (int e = 0; e < NE; e++) {
                    acc[m][e] += xv.x * wv[e].x;
                    acc[m][e] += xv.y * wv[e].y;
                }
            }
        }
    }

    // ---- Prompt tail: 64 dims, lane handles 2 dims for all TPW tokens ----
    {
        const int po = 2 * lane;
        float2 wp[NE];
#pragma unroll
        for (int e = 0; e < NE; e++)
            wp[e] = *(const float2*)&ws[e * WSTRIDE + MODEL_DIM + po];
#pragma unroll
        for (int m = 0; m < TPW; m++) {
            const float2 pv = *(const float2*)(prompt + (size_t)(tbase + m) * PROMPT_DIM + po);
#pragma unroll
            for (int e = 0; e < NE; e++) {
                acc[m][e] += pv.x * wp[e].x;
                acc[m][e] += pv.y * wp[e].y;
            }
        }
    }

    // ---- Warp butterfly reduction over lanes ----
#pragma unroll
    for (int off = 16; off > 0; off >>= 1) {
#pragma unroll
        for (int m = 0; m < TPW; m++)
#pragma unroll
            for (int e = 0; e < NE; e++)
                acc[m][e] += __shfl_xor_sync(0xffffffffu, acc[m][e], off);
    }

    // ---- Epilogue: lane m handles token (tbase + m) ----
    if (lane < TPW) {
        const int t = tbase + lane;

        float lg[NE];
#pragma unroll
        for (int m = 0; m < TPW; m++) {
            if (lane == m) {
#pragma unroll
                for (int e = 0; e < NE; e++) lg[e] = acc[m][e];
            }
        }
#pragma unroll
        for (int e = 0; e < NE; e++) lg[e] += b[e];

        // Top-2 with first-index tie-break (matches jax.lax.top_k)
        int i0 = 0; float m0 = lg[0];
#pragma unroll
        for (int e = 1; e < NE; e++)
            if (lg[e] > m0) { m0 = lg[e]; i0 = e; }
        int i1 = -1; float m1 = -INFINITY;
#pragma unroll
        for (int e = 0; e < NE; e++)
            if (e != i0 && lg[e] > m1) { m1 = lg[e]; i1 = e; }

        // Softmax over 8 (max-subtracted), gather top-2, renormalize with EPS clamp
        float s = 0.0f;
#pragma unroll
        for (int e = 0; e < NE; e++) s += __expf(lg[e] - m0);
        const float g0 = 1.0f / s;
        const float g1 = __expf(m1 - m0) / s;
        const float denom = fmaxf(g0 + g1, 1.1920929e-07f);
        const float r0 = g0 / denom;
        const float r1 = g1 / denom;

        // masks: [T, 2, 8] at offset 0
        float* mrow = out + (size_t)t * 16;
        const float4 z = make_float4(0.f, 0.f, 0.f, 0.f);
        *(float4*)(mrow + 0)  = z;
        *(float4*)(mrow + 4)  = z;
        *(float4*)(mrow + 8)  = z;
        *(float4*)(mrow + 12) = z;
        mrow[i0]     = 1.0f;
        mrow[8 + i1] = 1.0f;

        // gates_s: [T, 2] at offset T*16
        float* grow = out + (size_t)TOKENS * 16 + (size_t)t * 2;
        grow[0] = r0;
        grow[1] = r1;
    }
}

extern "C" void kernel_launch(void* const* d_in, const int* in_sizes, int n_in,
                              void* d_out, int out_size)
{
    const float* x      = (const float*)d_in[0];
    const float* prompt = (const float*)d_in[1];
    const float* W      = (const float*)d_in[2];
    const float* b      = (const float*)d_in[3];
    float* out          = (float*)d_out;

    cudaFuncSetAttribute(topkgate_kernel,
                         cudaFuncAttributeMaxDynamicSharedMemorySize, SMEM_BYTES);

    dim3 grid(TOKENS / TPB);   // 128 blocks, one wave
    topkgate_kernel<<<grid, THREADS, SMEM_BYTES>>>(x, prompt, W, b, out);
}

// round 5
// speedup vs baseline: 1.4398x; 1.0087x over previous
#include <cuda_runtime.h>
#include <math.h>

#define TOKENS     8192
#define MODEL_DIM  4096
#define PROMPT_DIM 64
#define KTOT       (MODEL_DIM + PROMPT_DIM)   // 4160
#define NE         8
#define NP         4                          // expert pairs
#define TPW        4                          // tokens per warp
#define WARPS      16
#define TPB        (TPW * WARPS)              // 64 tokens per block
#define THREADS    512
#define DSTRIDE    4162                       // per-pair row, float2 units (16B-aligned rows)
#define SMEM_BYTES (NP * DSTRIDE * 8)         // 133,184 B
#define CHUNK      64                         // dims per K-chunk (float2 per lane)
#define NIT        (MODEL_DIM / CHUNK)        // 64
#define RING       4                          // prefetch distance 3

// d = a*b + d elementwise on packed fp32x2
__device__ __forceinline__ void ffma2(unsigned long long& d,
                                      unsigned long long a,
                                      unsigned long long b) {
    asm("fma.rn.f32x2 %0, %1, %2, %0;" : "+l"(d) : "l"(a), "l"(b));
}
__device__ __forceinline__ unsigned long long dup2(float v) {
    unsigned long long r;
    asm("mov.b64 %0, {%1, %1};" : "=l"(r) : "f"(v));
    return r;
}
__device__ __forceinline__ void unpack2(unsigned long long v, float& lo, float& hi) {
    asm("mov.b64 {%0, %1}, %2;" : "=f"(lo), "=f"(hi) : "l"(v));
}

__global__ __launch_bounds__(THREADS, 1)
void topkgate_kernel(const float* __restrict__ x,
                     const float* __restrict__ prompt,
                     const float* __restrict__ W,
                     const float* __restrict__ b,
                     float* __restrict__ out)
{
    extern __shared__ float2 wsp[];   // wsp[p * DSTRIDE + d] = (W[d][2p], W[d][2p+1])

    const int tid = threadIdx.x;

    // ---- Stage W into expert-paired SMEM layout ----
    {
        const float2* Wv = (const float2*)W;   // Wv[d*4 + p] = (W[d][2p], W[d][2p+1])
        for (int i = tid; i < KTOT * NP; i += THREADS) {
            int d = i >> 2;
            int p = i & 3;
            wsp[p * DSTRIDE + d] = Wv[i];
        }
    }
    __syncthreads();

    const int w     = tid >> 5;
    const int lane  = tid & 31;
    const int tbase = blockIdx.x * TPB + w * TPW;   // grid covers TOKENS exactly

    const float* xr[TPW];
#pragma unroll
    for (int m = 0; m < TPW; m++)
        xr[m] = x + (size_t)(tbase + m) * MODEL_DIM + 2 * lane;

    // Packed accumulators: acc[m][p] = (logit[2p], logit[2p+1]) partial sums
    unsigned long long acc[TPW][NP];
#pragma unroll
    for (int m = 0; m < TPW; m++)
#pragma unroll
        for (int p = 0; p < NP; p++) acc[m][p] = 0ull;

    // ---- 4-deep register ring, prefetch distance 3 ----
    float2 buf[RING][TPW];
#pragma unroll
    for (int q = 0; q < RING - 1; q++)
#pragma unroll
        for (int m = 0; m < TPW; m++)
            buf[q][m] = __ldcs((const float2*)(xr[m] + q * CHUNK));

    for (int it = 0; it < NIT; it += RING) {
#pragma unroll
        for (int u = 0; u < RING; u++) {
            const int j = it + u;

            // Prefetch chunk j+3 into ring slot (u+3)&3
            if (j + (RING - 1) < NIT) {
#pragma unroll
                for (int m = 0; m < TPW; m++)
                    buf[(u + RING - 1) & (RING - 1)][m] =
                        __ldcs((const float2*)(xr[m] + (j + RING - 1) * CHUNK));
            }

            // W slice: dims (d0, d0+1) for all 4 expert pairs — LDS.128, conflict-free
            const int d0 = j * CHUNK + 2 * lane;
            ulonglong2 wv[NP];
#pragma unroll
            for (int p = 0; p < NP; p++)
                wv[p] = *(const ulonglong2*)&wsp[p * DSTRIDE + d0];
            // wv[p].x = (W[d0][2p],   W[d0][2p+1])
            // wv[p].y = (W[d0+1][2p], W[d0+1][2p+1])

#pragma unroll
            for (int m = 0; m < TPW; m++) {
                const float2 xv = buf[u][m];
                const unsigned long long xlo = dup2(xv.x);
                const unsigned long long xhi = dup2(xv.y);
#pragma unroll
                for (int p = 0; p < NP; p++) {
                    ffma2(acc[m][p], xlo, wv[p].x);
                    ffma2(acc[m][p], xhi, wv[p].y);
                }
            }
        }
    }

    // ---- Prompt tail: lane handles dims (4096+2*lane, +1) for all tokens ----
    {
        const int po = MODEL_DIM + 2 * lane;
        ulonglong2 wp[NP];
#pragma unroll
        for (int p = 0; p < NP; p++)
            wp[p] = *(const ulonglong2*)&wsp[p * DSTRIDE + po];
#pragma unroll
        for (int m = 0; m < TPW; m++) {
            const float2 pv = *(const float2*)(prompt + (size_t)(tbase + m) * PROMPT_DIM + 2 * lane);
            const unsigned long long plo = dup2(pv.x);
            const unsigned long long phi = dup2(pv.y);
#pragma unroll
            for (int p = 0; p < NP; p++) {
                ffma2(acc[m][p], plo, wp[p].x);
                ffma2(acc[m][p], phi, wp[p].y);
            }
        }
    }

    // ---- Unpack to scalar accumulators ----
    float accf[TPW][NE];
#pragma unroll
    for (int m = 0; m < TPW; m++)
#pragma unroll
        for (int p = 0; p < NP; p++)
            unpack2(acc[m][p], accf[m][2 * p], accf[m][2 * p + 1]);

    // ---- Warp butterfly reduction over lanes ----
#pragma unroll
    for (int off = 16; off > 0; off >>= 1) {
#pragma unroll
        for (int m = 0; m < TPW; m++)
#pragma unroll
            for (int e = 0; e < NE; e++)
                accf[m][e] += __shfl_xor_sync(0xffffffffu, accf[m][e], off);
    }

    // ---- Epilogue: lane m handles token (tbase + m) ----
    if (lane < TPW) {
        const int t = tbase + lane;

        float lg[NE];
#pragma unroll
        for (int m = 0; m < TPW; m++) {
            if (lane == m) {
#pragma unroll
                for (int e = 0; e < NE; e++) lg[e] = accf[m][e];
            }
        }
#pragma unroll
        for (int e = 0; e < NE; e++) lg[e] += b[e];

        // Top-2 with first-index tie-break (matches jax.lax.top_k)
        int i0 = 0; float m0 = lg[0];
#pragma unroll
        for (int e = 1; e < NE; e++)
            if (lg[e] > m0) { m0 = lg[e]; i0 = e; }
        int i1 = -1; float m1 = -INFINITY;
#pragma unroll
        for (int e = 0; e < NE; e++)
            if (e != i0 && lg[e] > m1) { m1 = lg[e]; i1 = e; }

        // Softmax over 8 (max-subtracted), gather top-2, renormalize with EPS clamp
        float s = 0.0f;
#pragma unroll
        for (int e = 0; e < NE; e++) s += __expf(lg[e] - m0);
        const float g0 = 1.0f / s;
        const float g1 = __expf(m1 - m0) / s;
        const float denom = fmaxf(g0 + g1, 1.1920929e-07f);
        const float r0 = g0 / denom;
        const float r1 = g1 / denom;

        // masks: [T, 2, 8] at offset 0
        float* mrow = out + (size_t)t * 16;
        const float4 z = make_float4(0.f, 0.f, 0.f, 0.f);
        *(float4*)(mrow + 0)  = z;
        *(float4*)(mrow + 4)  = z;
        *(float4*)(mrow + 8)  = z;
        *(float4*)(mrow + 12) = z;
        mrow[i0]     = 1.0f;
        mrow[8 + i1] = 1.0f;

        // gates_s: [T, 2] at offset T*16
        float* grow = out + (size_t)TOKENS * 16 + (size_t)t * 2;
        grow[0] = r0;
        grow[1] = r1;
    }
}

extern "C" void kernel_launch(void* const* d_in, const int* in_sizes, int n_in,
                              void* d_out, int out_size)
{
    const float* x      = (const float*)d_in[0];
    const float* prompt = (const float*)d_in[1];
    const float* W      = (const float*)d_in[2];
    const float* b      = (const float*)d_in[3];
    float* out          = (float*)d_out;

    cudaFuncSetAttribute(topkgate_kernel,
                         cudaFuncAttributeMaxDynamicSharedMemorySize, SMEM_BYTES);

    dim3 grid(TOKENS / TPB);   // 128 blocks, one wave
    topkgate_kernel<<<grid, THREADS, SMEM_BYTES>>>(x, prompt, W, b, out);
}

// round 6
// speedup vs baseline: 1.4468x; 1.0048x over previous
#include <cuda_runtime.h>
#include <math.h>

#define TOKENS     8192
#define MODEL_DIM  4096
#define PROMPT_DIM 64
#define KTOT       (MODEL_DIM + PROMPT_DIM)   // 4160
#define NE         8
#define NP         4                          // expert pairs
#define TPW        2                          // tokens per warp
#define WARPS      32
#define TPB        (TPW * WARPS)              // 64 tokens per block
#define THREADS    1024
#define DSTRIDE    4162                       // per-pair row, float2 units (16B-aligned rows)
#define SMEM_BYTES (NP * DSTRIDE * 8)         // 133,184 B
#define CHUNK      64                         // dims per K-chunk (float2 per lane)
#define NIT        (MODEL_DIM / CHUNK)        // 64
#define RING       4                          // prefetch distance 3

// d = a*b + d elementwise on packed fp32x2
__device__ __forceinline__ void ffma2(unsigned long long& d,
                                      unsigned long long a,
                                      unsigned long long b) {
    asm("fma.rn.f32x2 %0, %1, %2, %0;" : "+l"(d) : "l"(a), "l"(b));
}
__device__ __forceinline__ unsigned long long dup2(float v) {
    unsigned long long r;
    asm("mov.b64 %0, {%1, %1};" : "=l"(r) : "f"(v));
    return r;
}
__device__ __forceinline__ void unpack2(unsigned long long v, float& lo, float& hi) {
    asm("mov.b64 {%0, %1}, %2;" : "=f"(lo), "=f"(hi) : "l"(v));
}

__global__ __launch_bounds__(THREADS, 1)
void topkgate_kernel(const float* __restrict__ x,
                     const float* __restrict__ prompt,
                     const float* __restrict__ W,
                     const float* __restrict__ b,
                     float* __restrict__ out)
{
    extern __shared__ float2 wsp[];   // wsp[p * DSTRIDE + d] = (W[d][2p], W[d][2p+1])

    const int tid = threadIdx.x;

    // ---- Stage W into expert-paired SMEM layout ----
    {
        const float2* Wv = (const float2*)W;   // Wv[d*4 + p] = (W[d][2p], W[d][2p+1])
        for (int i = tid; i < KTOT * NP; i += THREADS) {
            int d = i >> 2;
            int p = i & 3;
            wsp[p * DSTRIDE + d] = Wv[i];
        }
    }
    __syncthreads();

    const int w     = tid >> 5;
    const int lane  = tid & 31;
    const int tbase = blockIdx.x * TPB + w * TPW;   // grid covers TOKENS exactly

    const float* xr0 = x + (size_t)(tbase + 0) * MODEL_DIM + 2 * lane;
    const float* xr1 = x + (size_t)(tbase + 1) * MODEL_DIM + 2 * lane;

    // Packed accumulators: acc[m][p] = (logit[2p], logit[2p+1]) partial sums
    unsigned long long acc[TPW][NP];
#pragma unroll
    for (int m = 0; m < TPW; m++)
#pragma unroll
        for (int p = 0; p < NP; p++) acc[m][p] = 0ull;

    // ---- 4-deep register ring, prefetch distance 3 ----
    float2 buf[RING][TPW];
#pragma unroll
    for (int q = 0; q < RING - 1; q++) {
        buf[q][0] = __ldcs((const float2*)(xr0 + q * CHUNK));
        buf[q][1] = __ldcs((const float2*)(xr1 + q * CHUNK));
    }

    for (int it = 0; it < NIT; it += RING) {
#pragma unroll
        for (int u = 0; u < RING; u++) {
            const int j = it + u;

            // Prefetch chunk j+3 into ring slot (u+3)&3
            if (j + (RING - 1) < NIT) {
                buf[(u + RING - 1) & (RING - 1)][0] =
                    __ldcs((const float2*)(xr0 + (j + RING - 1) * CHUNK));
                buf[(u + RING - 1) & (RING - 1)][1] =
                    __ldcs((const float2*)(xr1 + (j + RING - 1) * CHUNK));
            }

            // W slice: dims (d0, d0+1) for all 4 expert pairs — LDS.128, conflict-free
            const int d0 = j * CHUNK + 2 * lane;
            ulonglong2 wv[NP];
#pragma unroll
            for (int p = 0; p < NP; p++)
                wv[p] = *(const ulonglong2*)&wsp[p * DSTRIDE + d0];
            // wv[p].x = (W[d0][2p],   W[d0][2p+1])
            // wv[p].y = (W[d0+1][2p], W[d0+1][2p+1])

#pragma unroll
            for (int m = 0; m < TPW; m++) {
                const float2 xv = buf[u][m];
                const unsigned long long xlo = dup2(xv.x);
                const unsigned long long xhi = dup2(xv.y);
#pragma unroll
                for (int p = 0; p < NP; p++) {
                    ffma2(acc[m][p], xlo, wv[p].x);
                    ffma2(acc[m][p], xhi, wv[p].y);
                }
            }
        }
    }

    // ---- Prompt tail: lane handles dims (4096+2*lane, +1) for both tokens ----
    {
        const int po = MODEL_DIM + 2 * lane;
        ulonglong2 wp[NP];
#pragma unroll
        for (int p = 0; p < NP; p++)
            wp[p] = *(const ulonglong2*)&wsp[p * DSTRIDE + po];
#pragma unroll
        for (int m = 0; m < TPW; m++) {
            const float2 pv = *(const float2*)(prompt + (size_t)(tbase + m) * PROMPT_DIM + 2 * lane);
            const unsigned long long plo = dup2(pv.x);
            const unsigned long long phi = dup2(pv.y);
#pragma unroll
            for (int p = 0; p < NP; p++) {
                ffma2(acc[m][p], plo, wp[p].x);
                ffma2(acc[m][p], phi, wp[p].y);
            }
        }
    }

    // ---- Unpack to scalar accumulators ----
    float accf[TPW][NE];
#pragma unroll
    for (int m = 0; m < TPW; m++)
#pragma unroll
        for (int p = 0; p < NP; p++)
            unpack2(acc[m][p], accf[m][2 * p], accf[m][2 * p + 1]);

    // ---- Warp butterfly reduction over lanes ----
#pragma unroll
    for (int off = 16; off > 0; off >>= 1) {
#pragma unroll
        for (int m = 0; m < TPW; m++)
#pragma unroll
            for (int e = 0; e < NE; e++)
                accf[m][e] += __shfl_xor_sync(0xffffffffu, accf[m][e], off);
    }

    // ---- Epilogue: lane m handles token (tbase + m) ----
    if (lane < TPW) {
        const int t = tbase + lane;

        float lg[NE];
#pragma unroll
        for (int m = 0; m < TPW; m++) {
            if (lane == m) {
#pragma unroll
                for (int e = 0; e < NE; e++) lg[e] = accf[m][e];
            }
        }
#pragma unroll
        for (int e = 0; e < NE; e++) lg[e] += b[e];

        // Top-2 with first-index tie-break (matches jax.lax.top_k)
        int i0 = 0; float m0 = lg[0];
#pragma unroll
        for (int e = 1; e < NE; e++)
            if (lg[e] > m0) { m0 = lg[e]; i0 = e; }
        int i1 = -1; float m1 = -INFINITY;
#pragma unroll
        for (int e = 0; e < NE; e++)
            if (e != i0 && lg[e] > m1) { m1 = lg[e]; i1 = e; }

        // Softmax over 8 (max-subtracted), gather top-2, renormalize with EPS clamp
        float s = 0.0f;
#pragma unroll
        for (int e = 0; e < NE; e++) s += __expf(lg[e] - m0);
        const float g0 = 1.0f / s;
        const float g1 = __expf(m1 - m0) / s;
        const float denom = fmaxf(g0 + g1, 1.1920929e-07f);
        const float r0 = g0 / denom;
        const float r1 = g1 / denom;

        // masks: [T, 2, 8] at offset 0
        float* mrow = out + (size_t)t * 16;
        const float4 z = make_float4(0.f, 0.f, 0.f, 0.f);
        *(float4*)(mrow + 0)  = z;
        *(float4*)(mrow + 4)  = z;
        *(float4*)(mrow + 8)  = z;
        *(float4*)(mrow + 12) = z;
        mrow[i0]     = 1.0f;
        mrow[8 + i1] = 1.0f;

        // gates_s: [T, 2] at offset T*16
        float* grow = out + (size_t)TOKENS * 16 + (size_t)t * 2;
        grow[0] = r0;
        grow[1] = r1;
    }
}

extern "C" void kernel_launch(void* const* d_in, const int* in_sizes, int n_in,
                              void* d_out, int out_size)
{
    const float* x      = (const float*)d_in[0];
    const float* prompt = (const float*)d_in[1];
    const float* W      = (const float*)d_in[2];
    const float* b      = (const float*)d_in[3];
    float* out          = (float*)d_out;

    cudaFuncSetAttribute(topkgate_kernel,
                         cudaFuncAttributeMaxDynamicSharedMemorySize, SMEM_BYTES);

    dim3 grid(TOKENS / TPB);   // 128 blocks, one wave
    topkgate_kernel<<<grid, THREADS, SMEM_BYTES>>>(x, prompt, W, b, out);
}